// round 1
// baseline (speedup 1.0000x reference)
#include <cuda_runtime.h>
#include <cuda_bf16.h>
#include <cstdint>

#define BB   512
#define SEQL 512
#define IND  128
#define HID  256
#define TT   24
#define TEMP 64

// ---------------- persistent device scratch (no allocations) ----------------
__device__ __nv_bfloat16 g_H16[(size_t)BB * SEQL * IND];   // 67 MB, L2-resident
__device__ float g_h[BB * HID];
__device__ float g_c[BB * HID];
__device__ float g_y[BB];
__device__ float g_ctx[BB * IND];
__device__ float g_gates[BB * 4 * HID];

// ---------------- mma / ldmatrix helpers ----------------
__device__ __forceinline__ void ldsm4(uint32_t* r, uint32_t a) {
    asm volatile("ldmatrix.sync.aligned.m8n8.x4.shared.b16 {%0,%1,%2,%3}, [%4];\n"
        : "=r"(r[0]), "=r"(r[1]), "=r"(r[2]), "=r"(r[3]) : "r"(a));
}
__device__ __forceinline__ void ldsm4t(uint32_t* r, uint32_t a) {
    asm volatile("ldmatrix.sync.aligned.m8n8.x4.trans.shared.b16 {%0,%1,%2,%3}, [%4];\n"
        : "=r"(r[0]), "=r"(r[1]), "=r"(r[2]), "=r"(r[3]) : "r"(a));
}
__device__ __forceinline__ void mma_bf16(float* d, const uint32_t* a, const uint32_t* b) {
    asm volatile("mma.sync.aligned.m16n8k16.row.col.f32.bf16.bf16.f32 "
        "{%0,%1,%2,%3}, {%4,%5,%6,%7}, {%8,%9}, {%0,%1,%2,%3};\n"
        : "+f"(d[0]), "+f"(d[1]), "+f"(d[2]), "+f"(d[3])
        : "r"(a[0]), "r"(a[1]), "r"(a[2]), "r"(a[3]), "r"(b[0]), "r"(b[1]));
}

// ---------------- kernel 0: H fp32 -> bf16 ----------------
__global__ void convert_H(const float* __restrict__ H) {
    int i = blockIdx.x * blockDim.x + threadIdx.x;   // 8,388,608 threads, 4 elems each
    float4 v = ((const float4*)H)[i];
    __nv_bfloat162 lo = __floats2bfloat162_rn(v.x, v.y);
    __nv_bfloat162 hi = __floats2bfloat162_rn(v.z, v.w);
    uint2 o;
    o.x = *(const uint32_t*)&lo;
    o.y = *(const uint32_t*)&hi;
    ((uint2*)g_H16)[i] = o;
}

// ---------------- kernel 1: init state ----------------
__global__ void init_state(const float* __restrict__ emb, const float* __restrict__ y0) {
    int b = blockIdx.x, j = threadIdx.x;
    g_h[b * HID + j] = emb[b * 2 * HID + j];
    g_c[b * HID + j] = emb[b * 2 * HID + HID + j];
    if (j == 0) g_y[b] = y0[b];
}

// ---------------- kernel 2: fused attention (scores + softmax + ctx) ----------------
// one block per batch element. smem: H_b tile (512x136 bf16), Wa_t (128x72 bf16),
// cUa+ba (64), Va (64), e/beta (512), ctx partial (128), reduce (32)
#define SH_STRIDE 136
#define SW_STRIDE 72
#define ATTN_SMEM (SEQL*SH_STRIDE*2 + IND*SW_STRIDE*2 + (64 + 64 + 512 + 128 + 32) * 4)

__global__ __launch_bounds__(256, 1) void attn_kernel(
    const float* __restrict__ Wa, const float* __restrict__ Ua,
    const float* __restrict__ ba, const float* __restrict__ Va, int t)
{
    extern __shared__ char smraw[];
    __nv_bfloat16* sH = (__nv_bfloat16*)smraw;                          // [512][136]
    __nv_bfloat16* sW = (__nv_bfloat16*)(smraw + SEQL * SH_STRIDE * 2); // [128][72]
    float* scb  = (float*)(smraw + SEQL * SH_STRIDE * 2 + IND * SW_STRIDE * 2); // 64
    float* sVa  = scb + 64;     // 64
    float* se   = sVa + 64;     // 512 (also temp for cUa partials)
    float* sctx = se + 512;     // 128
    float* sred = sctx + 128;   // 32

    int b = blockIdx.x, tid = threadIdx.x;
    int warp = tid >> 5, lane = tid & 31;

    // --- cUa partials: 4 partitions x 64 k, into se[0..255] temp ---
    {
        int k = tid & 63, part = tid >> 6;
        const float* Uc = Ua + (size_t)t * 64 + k;
        const float* cb = g_c + b * HID;
        float a = 0.f;
        int j0 = part * 64;
        #pragma unroll 8
        for (int j = j0; j < j0 + 64; j++) a += cb[j] * Uc[(size_t)j * (TT * 64)];
        se[part * 64 + k] = a;
    }
    // --- load H_b bf16 tile into smem (padded rows) ---
    {
        const uint4* src = (const uint4*)(g_H16 + (size_t)b * SEQL * IND);
        uint4* dst = (uint4*)sH;
        #pragma unroll 4
        for (int i = tid; i < SEQL * IND / 8; i += 256) {
            int l = i >> 4, c = i & 15;        // 16 uint4 per row
            dst[l * (SH_STRIDE / 8) + c] = src[i];
        }
    }
    // --- load Wa_t -> bf16 smem ---
    #pragma unroll 4
    for (int i = tid; i < IND * 64; i += 256) {
        int j = i >> 6, k = i & 63;
        sW[j * SW_STRIDE + k] = __float2bfloat16(Wa[(size_t)j * (TT * 64) + t * 64 + k]);
    }
    if (tid < 64) sVa[tid] = Va[tid * TT + t];
    __syncthreads();
    if (tid < 64) {
        scb[tid] = ba[t * 64 + tid] + se[tid] + se[64 + tid] + se[128 + tid] + se[192 + tid];
    }
    __syncthreads();

    // --- S = H_b @ Wa_t via mma.sync, warp w owns rows [64w, 64w+64) ---
    uint32_t shBase = (uint32_t)__cvta_generic_to_shared(sH);
    uint32_t swBase = (uint32_t)__cvta_generic_to_shared(sW);
    int R = warp * 64;
    float acc[4][8][4];
    #pragma unroll
    for (int mi = 0; mi < 4; mi++)
        #pragma unroll
        for (int ni = 0; ni < 8; ni++)
            #pragma unroll
            for (int r = 0; r < 4; r++) acc[mi][ni][r] = 0.f;

    int lr = lane & 7, lg = (lane >> 3) & 1, lc = lane >> 4;
    #pragma unroll
    for (int ks = 0; ks < 8; ks++) {
        uint32_t afr[4][4];
        #pragma unroll
        for (int mi = 0; mi < 4; mi++) {
            int row = R + mi * 16 + lr + lg * 8;
            int col = ks * 16 + lc * 8;
            ldsm4(afr[mi], shBase + (row * SH_STRIDE + col) * 2);
        }
        uint32_t bfr[4][4];
        #pragma unroll
        for (int p = 0; p < 4; p++) {
            int row = ks * 16 + lr + lg * 8;
            int col = p * 16 + lc * 8;
            ldsm4t(bfr[p], swBase + (row * SW_STRIDE + col) * 2);
        }
        #pragma unroll
        for (int mi = 0; mi < 4; mi++)
            #pragma unroll
            for (int p = 0; p < 4; p++) {
                mma_bf16(acc[mi][2 * p],     afr[mi], &bfr[p][0]);
                mma_bf16(acc[mi][2 * p + 1], afr[mi], &bfr[p][2]);
            }
    }

    // --- epilogue: e[l] = sum_k Va[k]*tanh(S[l,k] + cUa[k] + ba[k]) ---
    {
        int q = lane & 3, gg = lane >> 2;
        #pragma unroll
        for (int mi = 0; mi < 4; mi++) {
            float s0 = 0.f, s1 = 0.f;
            #pragma unroll
            for (int ni = 0; ni < 8; ni++) {
                int k0 = ni * 8 + 2 * q;
                float va0 = sVa[k0], va1 = sVa[k0 + 1];
                float c0 = scb[k0],  c1 = scb[k0 + 1];
                s0 += va0 * tanhf(acc[mi][ni][0] + c0) + va1 * tanhf(acc[mi][ni][1] + c1);
                s1 += va0 * tanhf(acc[mi][ni][2] + c0) + va1 * tanhf(acc[mi][ni][3] + c1);
            }
            s0 += __shfl_xor_sync(0xffffffffu, s0, 1);
            s0 += __shfl_xor_sync(0xffffffffu, s0, 2);
            s1 += __shfl_xor_sync(0xffffffffu, s1, 1);
            s1 += __shfl_xor_sync(0xffffffffu, s1, 2);
            if (q == 0) {
                se[R + mi * 16 + gg]     = s0;
                se[R + mi * 16 + gg + 8] = s1;
            }
        }
    }
    __syncthreads();

    // --- softmax over 512 (scale 1/16) ---
    float e0 = se[tid], e1 = se[tid + 256];
    float m = fmaxf(e0, e1);
    #pragma unroll
    for (int off = 16; off; off >>= 1) m = fmaxf(m, __shfl_xor_sync(0xffffffffu, m, off));
    if (lane == 0) sred[warp] = m;
    __syncthreads();
    float M = fmaxf(fmaxf(fmaxf(sred[0], sred[1]), fmaxf(sred[2], sred[3])),
                    fmaxf(fmaxf(sred[4], sred[5]), fmaxf(sred[6], sred[7])));
    float v0 = expf((e0 - M) * 0.0625f);
    float v1 = expf((e1 - M) * 0.0625f);
    float s = v0 + v1;
    #pragma unroll
    for (int off = 16; off; off >>= 1) s += __shfl_xor_sync(0xffffffffu, s, off);
    if (lane == 0) sred[8 + warp] = s;
    se[tid] = v0; se[tid + 256] = v1;
    __syncthreads();
    float inv = 1.f / (sred[8] + sred[9] + sred[10] + sred[11] +
                       sred[12] + sred[13] + sred[14] + sred[15]);

    // --- ctx[d] = sum_l beta[l] * H[b,l,d] (from bf16 smem tile) ---
    {
        int d0 = tid & 127, hh = tid >> 7;
        float a = 0.f;
        #pragma unroll 8
        for (int l = hh; l < SEQL; l += 2)
            a += se[l] * __bfloat162float(sH[l * SH_STRIDE + d0]);
        if (hh) sctx[d0] = a;
        __syncthreads();
        if (!hh) g_ctx[b * IND + d0] = (a + sctx[d0]) * inv;
    }
}

// ---------------- kernel 3: gates = ctx@W_t + h@U_t + bias + y*Wy_t (fp32) ----------------
__global__ __launch_bounds__(256) void gates_kernel(
    const float* __restrict__ W, const float* __restrict__ U,
    const float* __restrict__ bias, const float* __restrict__ Wy, int t)
{
    __shared__ float As[64][33];
    __shared__ float Bs[32][64];
    int tid = threadIdx.x;
    int tx = tid & 15, ty = tid >> 4;
    int n0 = blockIdx.x * 64, b0 = blockIdx.y * 64;
    float acc[4][4] = {};

    for (int kc = 0; kc < 12; kc++) {
        #pragma unroll
        for (int i = tid; i < 2048; i += 256) {
            int r = i >> 5, kk = i & 31;
            int kg = kc * 32 + kk;
            As[r][kk] = (kg < IND) ? g_ctx[(b0 + r) * IND + kg]
                                   : g_h[(b0 + r) * HID + kg - IND];
        }
        #pragma unroll
        for (int i = tid; i < 2048; i += 256) {
            int kk = i >> 6, n = i & 63;
            int kg = kc * 32 + kk;
            const float* Br = (kg < IND)
                ? (W + (size_t)kg * (TT * 1024) + (size_t)t * 1024)
                : (U + (size_t)(kg - IND) * (TT * 1024) + (size_t)t * 1024);
            Bs[kk][n] = Br[n0 + n];
        }
        __syncthreads();
        #pragma unroll
        for (int kk = 0; kk < 32; kk++) {
            float4 bv = *(const float4*)&Bs[kk][tx * 4];
            float a0 = As[ty * 4 + 0][kk];
            float a1 = As[ty * 4 + 1][kk];
            float a2 = As[ty * 4 + 2][kk];
            float a3 = As[ty * 4 + 3][kk];
            acc[0][0] += a0 * bv.x; acc[0][1] += a0 * bv.y; acc[0][2] += a0 * bv.z; acc[0][3] += a0 * bv.w;
            acc[1][0] += a1 * bv.x; acc[1][1] += a1 * bv.y; acc[1][2] += a1 * bv.z; acc[1][3] += a1 * bv.w;
            acc[2][0] += a2 * bv.x; acc[2][1] += a2 * bv.y; acc[2][2] += a2 * bv.z; acc[2][3] += a2 * bv.w;
            acc[3][0] += a3 * bv.x; acc[3][1] += a3 * bv.y; acc[3][2] += a3 * bv.z; acc[3][3] += a3 * bv.w;
        }
        __syncthreads();
    }
    float yb[4];
    #pragma unroll
    for (int i = 0; i < 4; i++) yb[i] = g_y[b0 + ty * 4 + i];
    #pragma unroll
    for (int j = 0; j < 4; j++) {
        int n = n0 + tx * 4 + j;
        float bb = bias[t * 1024 + n], wy = Wy[t * 1024 + n];
        #pragma unroll
        for (int i = 0; i < 4; i++) {
            g_gates[(size_t)(b0 + ty * 4 + i) * 1024 + n] = acc[i][j] + bb + yb[i] * wy;
        }
    }
}

// ---------------- kernel 4: cell update + y projection + outputs ----------------
__global__ void update_kernel(const float* __restrict__ fcw, const float* __restrict__ fcb,
                              int t, float* __restrict__ outy, float* __restrict__ outh)
{
    __shared__ float red[8];
    int b = blockIdx.x, j = threadIdx.x;
    size_t gi = (size_t)b * 1024;
    float i_ = 1.f / (1.f + expf(-g_gates[gi + j]));
    float f_ = 1.f / (1.f + expf(-g_gates[gi + 256 + j]));
    float gv = tanhf(g_gates[gi + 512 + j]);
    float o_ = 1.f / (1.f + expf(-g_gates[gi + 768 + j]));
    float c = f_ * g_c[b * HID + j] + i_ * gv;
    float h = o_ * tanhf(c);
    g_c[b * HID + j] = c;
    g_h[b * HID + j] = h;
    outh[(size_t)b * TT * HID + (size_t)t * HID + j] = h;

    float p = h * fcw[t * HID + j];
    #pragma unroll
    for (int off = 16; off; off >>= 1) p += __shfl_xor_sync(0xffffffffu, p, off);
    int lane = j & 31, w = j >> 5;
    if (lane == 0) red[w] = p;
    __syncthreads();
    if (j == 0) {
        float ssum = red[0] + red[1] + red[2] + red[3] +
                     red[4] + red[5] + red[6] + red[7] + fcb[t];
        g_y[b] = ssum;
        outy[b * TT + t] = ssum;
    }
}

// ---------------- launch ----------------
extern "C" void kernel_launch(void* const* d_in, const int* in_sizes, int n_in,
                              void* d_out, int out_size)
{
    const float* H    = (const float*)d_in[0];
    const float* y0   = (const float*)d_in[1];
    const float* emb  = (const float*)d_in[2];
    const float* Wa   = (const float*)d_in[3];
    const float* Ua   = (const float*)d_in[4];
    const float* ba   = (const float*)d_in[5];
    const float* Va   = (const float*)d_in[6];
    const float* W    = (const float*)d_in[7];
    const float* U    = (const float*)d_in[8];
    const float* bias = (const float*)d_in[9];
    const float* Wy   = (const float*)d_in[10];
    const float* fcw  = (const float*)d_in[11];
    const float* fcb  = (const float*)d_in[12];

    float* outy = (float*)d_out;                 // (B, 24)
    float* outh = outy + (size_t)BB * TT;        // (B, 24, 256)

    // Idempotent; errors ignored (first non-captured call sets it persistently).
    cudaFuncSetAttribute(attn_kernel, cudaFuncAttributeMaxDynamicSharedMemorySize, ATTN_SMEM);

    convert_H<<<(BB * SEQL * IND / 4) / 256, 256>>>(H);
    init_state<<<BB, 256>>>(emb, y0);
    for (int t = 0; t < TT; t++) {
        attn_kernel<<<BB, 256, ATTN_SMEM>>>(Wa, Ua, ba, Va, t);
        gates_kernel<<<dim3(16, 8), 256>>>(W, U, bias, Wy, t);
        update_kernel<<<BB, 256>>>(fcw, fcb, t, outy, outh);
    }
}

// round 2
// speedup vs baseline: 1.2435x; 1.2435x over previous
#include <cuda_runtime.h>
#include <cuda_bf16.h>
#include <cstdint>

#define BB   512
#define SEQL 512
#define IND  128
#define HID  256
#define TT   24
#define TEMP 64

// ---------------- persistent device scratch (no allocations) ----------------
__device__ __nv_bfloat16 g_H16[(size_t)BB * SEQL * IND];   // 67 MB, L2-resident
__device__ float g_h[BB * HID];
__device__ float g_c[BB * HID];
__device__ float g_y[BB];
__device__ float g_ctx[BB * IND];
__device__ float g_gates[BB * 4 * HID];

// ---------------- mma / ldmatrix helpers ----------------
__device__ __forceinline__ void ldsm4(uint32_t* r, uint32_t a) {
    asm volatile("ldmatrix.sync.aligned.m8n8.x4.shared.b16 {%0,%1,%2,%3}, [%4];\n"
        : "=r"(r[0]), "=r"(r[1]), "=r"(r[2]), "=r"(r[3]) : "r"(a));
}
__device__ __forceinline__ void ldsm4t(uint32_t* r, uint32_t a) {
    asm volatile("ldmatrix.sync.aligned.m8n8.x4.trans.shared.b16 {%0,%1,%2,%3}, [%4];\n"
        : "=r"(r[0]), "=r"(r[1]), "=r"(r[2]), "=r"(r[3]) : "r"(a));
}
__device__ __forceinline__ void mma_bf16(float* d, const uint32_t* a, const uint32_t* b) {
    asm volatile("mma.sync.aligned.m16n8k16.row.col.f32.bf16.bf16.f32 "
        "{%0,%1,%2,%3}, {%4,%5,%6,%7}, {%8,%9}, {%0,%1,%2,%3};\n"
        : "+f"(d[0]), "+f"(d[1]), "+f"(d[2]), "+f"(d[3])
        : "r"(a[0]), "r"(a[1]), "r"(a[2]), "r"(a[3]), "r"(b[0]), "r"(b[1]));
}
__device__ __forceinline__ void mma_tf32(float* d, const uint32_t* a, uint32_t b0, uint32_t b1) {
    asm volatile("mma.sync.aligned.m16n8k8.row.col.f32.tf32.tf32.f32 "
        "{%0,%1,%2,%3}, {%4,%5,%6,%7}, {%8,%9}, {%0,%1,%2,%3};\n"
        : "+f"(d[0]), "+f"(d[1]), "+f"(d[2]), "+f"(d[3])
        : "r"(a[0]), "r"(a[1]), "r"(a[2]), "r"(a[3]), "r"(b0), "r"(b1));
}
__device__ __forceinline__ uint32_t f2tf32(float v) {
    uint32_t u; asm("cvt.rna.tf32.f32 %0, %1;" : "=r"(u) : "f"(v)); return u;
}
__device__ __forceinline__ float fast_tanh(float x) {
    float r; asm("tanh.approx.f32 %0, %1;" : "=f"(r) : "f"(x)); return r;
}

// ---------------- kernel 0: H fp32 -> bf16 ----------------
__global__ void convert_H(const float* __restrict__ H) {
    int i = blockIdx.x * blockDim.x + threadIdx.x;
    float4 v = ((const float4*)H)[i];
    __nv_bfloat162 lo = __floats2bfloat162_rn(v.x, v.y);
    __nv_bfloat162 hi = __floats2bfloat162_rn(v.z, v.w);
    uint2 o;
    o.x = *(const uint32_t*)&lo;
    o.y = *(const uint32_t*)&hi;
    ((uint2*)g_H16)[i] = o;
}

// ---------------- kernel 1: init state ----------------
__global__ void init_state(const float* __restrict__ emb, const float* __restrict__ y0) {
    int b = blockIdx.x, j = threadIdx.x;
    g_h[b * HID + j] = emb[b * 2 * HID + j];
    g_c[b * HID + j] = emb[b * 2 * HID + HID + j];
    if (j == 0) g_y[b] = y0[b];
}

// ---------------- kernel 2: fused attention ----------------
#define SH_STRIDE 136
#define SW_STRIDE 72
// floats after the bf16 tiles: scb 64 | sVa 64 | se 512 | sctxp 2048 | sred 32
#define ATTN_F32_CNT (64 + 64 + 512 + 2048 + 32)
#define ATTN_SMEM (SEQL*SH_STRIDE*2 + IND*SW_STRIDE*2 + ATTN_F32_CNT * 4)

__global__ __launch_bounds__(256, 1) void attn_kernel(
    const float* __restrict__ Wa, const float* __restrict__ Ua,
    const float* __restrict__ ba, const float* __restrict__ Va, int t)
{
    extern __shared__ char smraw[];
    __nv_bfloat16* sH = (__nv_bfloat16*)smraw;                          // [512][136]
    __nv_bfloat16* sW = (__nv_bfloat16*)(smraw + SEQL * SH_STRIDE * 2); // [128][72]
    float* scb   = (float*)(smraw + SEQL * SH_STRIDE * 2 + IND * SW_STRIDE * 2); // 64
    float* sVa   = scb + 64;      // 64
    float* se    = sVa + 64;      // 512 (also temp for cUa partials)
    float* sctxp = se + 512;      // 16*128
    float* sred  = sctxp + 2048;  // 32

    int b = blockIdx.x, tid = threadIdx.x;
    int warp = tid >> 5, lane = tid & 31;

    // --- cUa partials ---
    {
        int k = tid & 63, part = tid >> 6;
        const float* Uc = Ua + (size_t)t * 64 + k;
        const float* cb = g_c + b * HID;
        float a = 0.f;
        int j0 = part * 64;
        #pragma unroll 8
        for (int j = j0; j < j0 + 64; j++) a += cb[j] * Uc[(size_t)j * (TT * 64)];
        se[part * 64 + k] = a;
    }
    // --- H_b bf16 tile -> smem ---
    {
        const uint4* src = (const uint4*)(g_H16 + (size_t)b * SEQL * IND);
        uint4* dst = (uint4*)sH;
        #pragma unroll 4
        for (int i = tid; i < SEQL * IND / 8; i += 256) {
            int l = i >> 4, c = i & 15;
            dst[l * (SH_STRIDE / 8) + c] = src[i];
        }
    }
    // --- Wa_t -> bf16 smem ---
    #pragma unroll 4
    for (int i = tid; i < IND * 64; i += 256) {
        int j = i >> 6, k = i & 63;
        sW[j * SW_STRIDE + k] = __float2bfloat16(Wa[(size_t)j * (TT * 64) + t * 64 + k]);
    }
    if (tid < 64) sVa[tid] = Va[tid * TT + t];
    __syncthreads();
    if (tid < 64) {
        scb[tid] = ba[t * 64 + tid] + se[tid] + se[64 + tid] + se[128 + tid] + se[192 + tid];
    }
    __syncthreads();

    // --- S = H_b @ Wa_t (bf16 mma), warp w owns rows [64w,64w+64) ---
    uint32_t shBase = (uint32_t)__cvta_generic_to_shared(sH);
    uint32_t swBase = (uint32_t)__cvta_generic_to_shared(sW);
    int R = warp * 64;
    float acc[4][8][4];
    #pragma unroll
    for (int mi = 0; mi < 4; mi++)
        #pragma unroll
        for (int ni = 0; ni < 8; ni++)
            #pragma unroll
            for (int r = 0; r < 4; r++) acc[mi][ni][r] = 0.f;

    int lr = lane & 7, lg = (lane >> 3) & 1, lc = lane >> 4;
    #pragma unroll
    for (int ks = 0; ks < 8; ks++) {
        uint32_t afr[4][4];
        #pragma unroll
        for (int mi = 0; mi < 4; mi++) {
            int row = R + mi * 16 + lr + lg * 8;
            int col = ks * 16 + lc * 8;
            ldsm4(afr[mi], shBase + (row * SH_STRIDE + col) * 2);
        }
        uint32_t bfr[4][4];
        #pragma unroll
        for (int p = 0; p < 4; p++) {
            int row = ks * 16 + lr + lg * 8;
            int col = p * 16 + lc * 8;
            ldsm4t(bfr[p], swBase + (row * SW_STRIDE + col) * 2);
        }
        #pragma unroll
        for (int mi = 0; mi < 4; mi++)
            #pragma unroll
            for (int p = 0; p < 4; p++) {
                mma_bf16(acc[mi][2 * p],     afr[mi], &bfr[p][0]);
                mma_bf16(acc[mi][2 * p + 1], afr[mi], &bfr[p][2]);
            }
    }

    // --- e[l] = sum_k Va[k]*tanh(S[l,k]+cUa[k]+ba[k]), HW tanh ---
    {
        int q = lane & 3, gg = lane >> 2;
        #pragma unroll
        for (int mi = 0; mi < 4; mi++) {
            float s0 = 0.f, s1 = 0.f;
            #pragma unroll
            for (int ni = 0; ni < 8; ni++) {
                int k0 = ni * 8 + 2 * q;
                float va0 = sVa[k0], va1 = sVa[k0 + 1];
                float c0 = scb[k0],  c1 = scb[k0 + 1];
                s0 += va0 * fast_tanh(acc[mi][ni][0] + c0) + va1 * fast_tanh(acc[mi][ni][1] + c1);
                s1 += va0 * fast_tanh(acc[mi][ni][2] + c0) + va1 * fast_tanh(acc[mi][ni][3] + c1);
            }
            s0 += __shfl_xor_sync(0xffffffffu, s0, 1);
            s0 += __shfl_xor_sync(0xffffffffu, s0, 2);
            s1 += __shfl_xor_sync(0xffffffffu, s1, 1);
            s1 += __shfl_xor_sync(0xffffffffu, s1, 2);
            if (q == 0) {
                se[R + mi * 16 + gg]     = s0;
                se[R + mi * 16 + gg + 8] = s1;
            }
        }
    }
    __syncthreads();

    // --- softmax over 512 (scale 1/16) ---
    float e0 = se[tid], e1 = se[tid + 256];
    float m = fmaxf(e0, e1);
    #pragma unroll
    for (int off = 16; off; off >>= 1) m = fmaxf(m, __shfl_xor_sync(0xffffffffu, m, off));
    if (lane == 0) sred[warp] = m;
    __syncthreads();
    float M = fmaxf(fmaxf(fmaxf(sred[0], sred[1]), fmaxf(sred[2], sred[3])),
                    fmaxf(fmaxf(sred[4], sred[5]), fmaxf(sred[6], sred[7])));
    float v0 = __expf((e0 - M) * 0.0625f);
    float v1 = __expf((e1 - M) * 0.0625f);
    float s = v0 + v1;
    #pragma unroll
    for (int off = 16; off; off >>= 1) s += __shfl_xor_sync(0xffffffffu, s, off);
    if (lane == 0) sred[8 + warp] = s;
    se[tid] = v0; se[tid + 256] = v1;
    __syncthreads();
    float inv = 1.f / (sred[8] + sred[9] + sred[10] + sred[11] +
                       sred[12] + sred[13] + sred[14] + sred[15]);

    // --- ctx[d] = sum_l beta[l]*H[b,l,d] — uint4 (8 bf16) loads, 16 partials ---
    {
        int q = tid & 15, part = tid >> 4;
        float a[8] = {0.f, 0.f, 0.f, 0.f, 0.f, 0.f, 0.f, 0.f};
        #pragma unroll 4
        for (int l = part; l < SEQL; l += 16) {
            float bl = se[l];
            uint4 v = *(const uint4*)(sH + l * SH_STRIDE + q * 8);
            const __nv_bfloat162* h2 = (const __nv_bfloat162*)&v;
            #pragma unroll
            for (int i = 0; i < 4; i++) {
                float2 f = __bfloat1622float2(h2[i]);
                a[2 * i]     += bl * f.x;
                a[2 * i + 1] += bl * f.y;
            }
        }
        #pragma unroll
        for (int i = 0; i < 8; i++) sctxp[part * 128 + q * 8 + i] = a[i];
        __syncthreads();
        if (tid < 128) {
            float sum = 0.f;
            #pragma unroll
            for (int p = 0; p < 16; p++) sum += sctxp[p * 128 + tid];
            g_ctx[b * IND + tid] = sum * inv;
        }
    }
}

// ---------------- kernel 3: gates via tf32 mma ----------------
// tile 64(batch) x 64(n), grid (16,8)=128 blocks, 256 thr = 8 warps (4 m x 2 n)
__global__ __launch_bounds__(256) void gates_kernel(
    const float* __restrict__ W, const float* __restrict__ U,
    const float* __restrict__ bias, const float* __restrict__ Wy, int t)
{
    __shared__ uint32_t As[64][36];
    __shared__ uint32_t Bs[32][72];
    int tid = threadIdx.x;
    int warp = tid >> 5, lane = tid & 31;
    int wm = warp & 3, wn = warp >> 2;
    int n0 = blockIdx.x * 64, b0 = blockIdx.y * 64;
    float acc[4][4] = {};

    for (int kc = 0; kc < 12; kc++) {
        #pragma unroll
        for (int i = tid; i < 2048; i += 256) {
            int r = i >> 5, kk = i & 31;
            int kg = kc * 32 + kk;
            float v = (kg < IND) ? g_ctx[(b0 + r) * IND + kg]
                                 : g_h[(b0 + r) * HID + kg - IND];
            As[r][kk] = f2tf32(v);
        }
        #pragma unroll
        for (int i = tid; i < 2048; i += 256) {
            int kk = i >> 6, n = i & 63;
            int kg = kc * 32 + kk;
            const float* Br = (kg < IND)
                ? (W + (size_t)kg * (TT * 1024) + (size_t)t * 1024)
                : (U + (size_t)(kg - IND) * (TT * 1024) + (size_t)t * 1024);
            Bs[kk][n] = f2tf32(Br[n0 + n]);
        }
        __syncthreads();
        int ar = wm * 16 + (lane >> 2);
        int bk = lane & 3;
        int bn = wn * 32 + (lane >> 2);
        #pragma unroll
        for (int ks = 0; ks < 4; ks++) {
            uint32_t a[4];
            int ac = ks * 8 + (lane & 3);
            a[0] = As[ar][ac];     a[1] = As[ar + 8][ac];
            a[2] = As[ar][ac + 4]; a[3] = As[ar + 8][ac + 4];
            #pragma unroll
            for (int nt = 0; nt < 4; nt++) {
                uint32_t b0r = Bs[ks * 8 + bk][bn + nt * 8];
                uint32_t b1r = Bs[ks * 8 + bk + 4][bn + nt * 8];
                mma_tf32(acc[nt], a, b0r, b1r);
            }
        }
        __syncthreads();
    }
    int r0 = b0 + wm * 16 + (lane >> 2);
    float y0v = g_y[r0], y1v = g_y[r0 + 8];
    #pragma unroll
    for (int nt = 0; nt < 4; nt++) {
        int n = n0 + wn * 32 + nt * 8 + (lane & 3) * 2;
        float bb0 = bias[t * 1024 + n],   bb1 = bias[t * 1024 + n + 1];
        float wy0 = Wy[t * 1024 + n],     wy1 = Wy[t * 1024 + n + 1];
        g_gates[(size_t)r0 * 1024 + n]           = acc[nt][0] + bb0 + y0v * wy0;
        g_gates[(size_t)r0 * 1024 + n + 1]       = acc[nt][1] + bb1 + y0v * wy1;
        g_gates[(size_t)(r0 + 8) * 1024 + n]     = acc[nt][2] + bb0 + y1v * wy0;
        g_gates[(size_t)(r0 + 8) * 1024 + n + 1] = acc[nt][3] + bb1 + y1v * wy1;
    }
}

// ---------------- kernel 4: cell update + y projection + outputs ----------------
__global__ void update_kernel(const float* __restrict__ fcw, const float* __restrict__ fcb,
                              int t, float* __restrict__ outy, float* __restrict__ outh)
{
    __shared__ float red[8];
    int b = blockIdx.x, j = threadIdx.x;
    size_t gi = (size_t)b * 1024;
    float i_ = 1.f / (1.f + expf(-g_gates[gi + j]));
    float f_ = 1.f / (1.f + expf(-g_gates[gi + 256 + j]));
    float gv = tanhf(g_gates[gi + 512 + j]);
    float o_ = 1.f / (1.f + expf(-g_gates[gi + 768 + j]));
    float c = f_ * g_c[b * HID + j] + i_ * gv;
    float h = o_ * tanhf(c);
    g_c[b * HID + j] = c;
    g_h[b * HID + j] = h;
    outh[(size_t)b * TT * HID + (size_t)t * HID + j] = h;

    float p = h * fcw[t * HID + j];
    #pragma unroll
    for (int off = 16; off; off >>= 1) p += __shfl_xor_sync(0xffffffffu, p, off);
    int lane = j & 31, w = j >> 5;
    if (lane == 0) red[w] = p;
    __syncthreads();
    if (j == 0) {
        float ssum = red[0] + red[1] + red[2] + red[3] +
                     red[4] + red[5] + red[6] + red[7] + fcb[t];
        g_y[b] = ssum;
        outy[b * TT + t] = ssum;
    }
}

// ---------------- launch ----------------
extern "C" void kernel_launch(void* const* d_in, const int* in_sizes, int n_in,
                              void* d_out, int out_size)
{
    const float* H    = (const float*)d_in[0];
    const float* y0   = (const float*)d_in[1];
    const float* emb  = (const float*)d_in[2];
    const float* Wa   = (const float*)d_in[3];
    const float* Ua   = (const float*)d_in[4];
    const float* ba   = (const float*)d_in[5];
    const float* Va   = (const float*)d_in[6];
    const float* W    = (const float*)d_in[7];
    const float* U    = (const float*)d_in[8];
    const float* bias = (const float*)d_in[9];
    const float* Wy   = (const float*)d_in[10];
    const float* fcw  = (const float*)d_in[11];
    const float* fcb  = (const float*)d_in[12];

    float* outy = (float*)d_out;                 // (B, 24)
    float* outh = outy + (size_t)BB * TT;        // (B, 24, 256)

    cudaFuncSetAttribute(attn_kernel, cudaFuncAttributeMaxDynamicSharedMemorySize, ATTN_SMEM);

    convert_H<<<(BB * SEQL * IND / 4) / 256, 256>>>(H);
    init_state<<<BB, 256>>>(emb, y0);
    for (int t = 0; t < TT; t++) {
        attn_kernel<<<BB, 256, ATTN_SMEM>>>(Wa, Ua, ba, Va, t);
        gates_kernel<<<dim3(16, 8), 256>>>(W, U, bias, Wy, t);
        update_kernel<<<BB, 256>>>(fcw, fcb, t, outy, outh);
    }
}

// round 3
// speedup vs baseline: 1.4801x; 1.1903x over previous
#include <cuda_runtime.h>
#include <cuda_bf16.h>
#include <cstdint>

#define BB   512
#define SEQL 512
#define IND  128
#define HID  256
#define TT   24
#define TEMP 64

// ---------------- persistent device scratch (no allocations) ----------------
__device__ __nv_bfloat16 g_H16[(size_t)BB * SEQL * IND];   // 67 MB, L2-resident
__device__ float g_h[BB * HID];
__device__ float g_c[BB * HID];
__device__ float g_y[BB];
__device__ float g_ctx[BB * IND];
__device__ float g_gates[BB * 4 * HID];

// ---------------- asm helpers ----------------
__device__ __forceinline__ void ldsm4(uint32_t* r, uint32_t a) {
    asm volatile("ldmatrix.sync.aligned.m8n8.x4.shared.b16 {%0,%1,%2,%3}, [%4];\n"
        : "=r"(r[0]), "=r"(r[1]), "=r"(r[2]), "=r"(r[3]) : "r"(a));
}
__device__ __forceinline__ void ldsm4t(uint32_t* r, uint32_t a) {
    asm volatile("ldmatrix.sync.aligned.m8n8.x4.trans.shared.b16 {%0,%1,%2,%3}, [%4];\n"
        : "=r"(r[0]), "=r"(r[1]), "=r"(r[2]), "=r"(r[3]) : "r"(a));
}
__device__ __forceinline__ void mma_bf16(float* d, const uint32_t* a, const uint32_t* b) {
    asm volatile("mma.sync.aligned.m16n8k16.row.col.f32.bf16.bf16.f32 "
        "{%0,%1,%2,%3}, {%4,%5,%6,%7}, {%8,%9}, {%0,%1,%2,%3};\n"
        : "+f"(d[0]), "+f"(d[1]), "+f"(d[2]), "+f"(d[3])
        : "r"(a[0]), "r"(a[1]), "r"(a[2]), "r"(a[3]), "r"(b[0]), "r"(b[1]));
}
__device__ __forceinline__ void mma_tf32(float* d, const uint32_t* a, uint32_t b0, uint32_t b1) {
    asm volatile("mma.sync.aligned.m16n8k8.row.col.f32.tf32.tf32.f32 "
        "{%0,%1,%2,%3}, {%4,%5,%6,%7}, {%8,%9}, {%0,%1,%2,%3};\n"
        : "+f"(d[0]), "+f"(d[1]), "+f"(d[2]), "+f"(d[3])
        : "r"(a[0]), "r"(a[1]), "r"(a[2]), "r"(a[3]), "r"(b0), "r"(b1));
}
__device__ __forceinline__ float fast_tanh(float x) {
    float r; asm("tanh.approx.f32 %0, %1;" : "=f"(r) : "f"(x)); return r;
}
__device__ __forceinline__ void cp_async16(uint32_t dst, const void* src) {
    asm volatile("cp.async.cg.shared.global [%0], [%1], 16;\n" :: "r"(dst), "l"(src));
}
__device__ __forceinline__ void cp_commit() {
    asm volatile("cp.async.commit_group;\n" ::: "memory");
}
template<int N> __device__ __forceinline__ void cp_wait() {
    asm volatile("cp.async.wait_group %0;\n" :: "n"(N) : "memory");
}

// ---------------- kernel 0: H fp32 -> bf16 ----------------
__global__ void convert_H(const float* __restrict__ H) {
    int i = blockIdx.x * blockDim.x + threadIdx.x;
    float4 v = ((const float4*)H)[i];
    __nv_bfloat162 lo = __floats2bfloat162_rn(v.x, v.y);
    __nv_bfloat162 hi = __floats2bfloat162_rn(v.z, v.w);
    uint2 o;
    o.x = *(const uint32_t*)&lo;
    o.y = *(const uint32_t*)&hi;
    ((uint2*)g_H16)[i] = o;
}

// ---------------- kernel 1: init state ----------------
__global__ void init_state(const float* __restrict__ emb, const float* __restrict__ y0) {
    int b = blockIdx.x, j = threadIdx.x;
    g_h[b * HID + j] = emb[b * 2 * HID + j];
    g_c[b * HID + j] = emb[b * 2 * HID + HID + j];
    if (j == 0) g_y[b] = y0[b];
}

// ---------------- kernel 2: fused attention ----------------
#define SH_STRIDE 136
#define SW_STRIDE 72
#define ATTN_F32_CNT (64 + 64 + 512 + 2048 + 32)
#define ATTN_SMEM (SEQL*SH_STRIDE*2 + IND*SW_STRIDE*2 + ATTN_F32_CNT * 4)

// one 16-col k-chunk of S = H @ Wa_t
__device__ __forceinline__ void attn_mma_chunk(
    int ks, int R, int lane, uint32_t shBase, uint32_t swBase, float acc[4][8][4])
{
    int lr = lane & 7, lg = (lane >> 3) & 1, lc = lane >> 4;
    uint32_t afr[4][4];
    #pragma unroll
    for (int mi = 0; mi < 4; mi++) {
        int row = R + mi * 16 + lr + lg * 8;
        int col = ks * 16 + lc * 8;
        ldsm4(afr[mi], shBase + (row * SH_STRIDE + col) * 2);
    }
    uint32_t bfr[4][4];
    #pragma unroll
    for (int p = 0; p < 4; p++) {
        int row = ks * 16 + lr + lg * 8;
        int col = p * 16 + lc * 8;
        ldsm4t(bfr[p], swBase + (row * SW_STRIDE + col) * 2);
    }
    #pragma unroll
    for (int mi = 0; mi < 4; mi++)
        #pragma unroll
        for (int p = 0; p < 4; p++) {
            mma_bf16(acc[mi][2 * p],     afr[mi], &bfr[p][0]);
            mma_bf16(acc[mi][2 * p + 1], afr[mi], &bfr[p][2]);
        }
}

__global__ __launch_bounds__(256, 1) void attn_kernel(
    const float* __restrict__ Wa, const float* __restrict__ Ua,
    const float* __restrict__ ba, const float* __restrict__ Va, int t)
{
    extern __shared__ char smraw[];
    __nv_bfloat16* sH = (__nv_bfloat16*)smraw;                          // [512][136]
    __nv_bfloat16* sW = (__nv_bfloat16*)(smraw + SEQL * SH_STRIDE * 2); // [128][72]
    float* scb   = (float*)(smraw + SEQL * SH_STRIDE * 2 + IND * SW_STRIDE * 2);
    float* sVa   = scb + 64;
    float* se    = sVa + 64;      // 512 (also temp for cUa partials)
    float* sctxp = se + 512;      // 16*128
    float* sred  = sctxp + 2048;  // 32

    int b = blockIdx.x, tid = threadIdx.x;
    int warp = tid >> 5, lane = tid & 31;
    uint32_t shBase = (uint32_t)__cvta_generic_to_shared(sH);
    uint32_t swBase = (uint32_t)__cvta_generic_to_shared(sW);

    // --- issue the whole H tile as 8 cp.async chunk-groups (16 cols each) ---
    {
        const __nv_bfloat16* srcB = g_H16 + (size_t)b * SEQL * IND;
        #pragma unroll
        for (int c = 0; c < 8; c++) {
            #pragma unroll
            for (int i = tid; i < 1024; i += 256) {
                int row = i >> 1, half = i & 1;
                uint32_t dst = shBase + (uint32_t)(row * SH_STRIDE + c * 16 + half * 8) * 2;
                cp_async16(dst, srcB + row * IND + c * 16 + half * 8);
            }
            cp_commit();
        }
    }

    // --- overlap: cUa partials ---
    {
        int k = tid & 63, part = tid >> 6;
        const float* Uc = Ua + (size_t)t * 64 + k;
        const float* cb = g_c + b * HID;
        float a = 0.f;
        int j0 = part * 64;
        #pragma unroll 8
        for (int j = j0; j < j0 + 64; j++) a += cb[j] * Uc[(size_t)j * (TT * 64)];
        se[part * 64 + k] = a;
    }
    // --- overlap: Wa_t -> bf16 smem ---
    #pragma unroll 4
    for (int i = tid; i < IND * 64; i += 256) {
        int j = i >> 6, k = i & 63;
        sW[j * SW_STRIDE + k] = __float2bfloat16(Wa[(size_t)j * (TT * 64) + t * 64 + k]);
    }
    if (tid < 64) sVa[tid] = Va[tid * TT + t];
    __syncthreads();
    if (tid < 64) {
        scb[tid] = ba[t * 64 + tid] + se[tid] + se[64 + tid] + se[128 + tid] + se[192 + tid];
    }
    __syncthreads();

    // --- S GEMM pipelined against the in-flight H chunks ---
    int R = warp * 64;
    float acc[4][8][4];
    #pragma unroll
    for (int mi = 0; mi < 4; mi++)
        #pragma unroll
        for (int ni = 0; ni < 8; ni++)
            #pragma unroll
            for (int r = 0; r < 4; r++) acc[mi][ni][r] = 0.f;

    cp_wait<7>(); __syncthreads(); attn_mma_chunk(0, R, lane, shBase, swBase, acc);
    cp_wait<6>(); __syncthreads(); attn_mma_chunk(1, R, lane, shBase, swBase, acc);
    cp_wait<5>(); __syncthreads(); attn_mma_chunk(2, R, lane, shBase, swBase, acc);
    cp_wait<4>(); __syncthreads(); attn_mma_chunk(3, R, lane, shBase, swBase, acc);
    cp_wait<3>(); __syncthreads(); attn_mma_chunk(4, R, lane, shBase, swBase, acc);
    cp_wait<2>(); __syncthreads(); attn_mma_chunk(5, R, lane, shBase, swBase, acc);
    cp_wait<1>(); __syncthreads(); attn_mma_chunk(6, R, lane, shBase, swBase, acc);
    cp_wait<0>(); __syncthreads(); attn_mma_chunk(7, R, lane, shBase, swBase, acc);

    // --- e[l] = sum_k Va[k]*tanh(S[l,k]+cUa[k]+ba[k]) ---
    {
        int q = lane & 3, gg = lane >> 2;
        #pragma unroll
        for (int mi = 0; mi < 4; mi++) {
            float s0 = 0.f, s1 = 0.f;
            #pragma unroll
            for (int ni = 0; ni < 8; ni++) {
                int k0 = ni * 8 + 2 * q;
                float va0 = sVa[k0], va1 = sVa[k0 + 1];
                float c0 = scb[k0],  c1 = scb[k0 + 1];
                s0 += va0 * fast_tanh(acc[mi][ni][0] + c0) + va1 * fast_tanh(acc[mi][ni][1] + c1);
                s1 += va0 * fast_tanh(acc[mi][ni][2] + c0) + va1 * fast_tanh(acc[mi][ni][3] + c1);
            }
            s0 += __shfl_xor_sync(0xffffffffu, s0, 1);
            s0 += __shfl_xor_sync(0xffffffffu, s0, 2);
            s1 += __shfl_xor_sync(0xffffffffu, s1, 1);
            s1 += __shfl_xor_sync(0xffffffffu, s1, 2);
            if (q == 0) {
                se[R + mi * 16 + gg]     = s0;
                se[R + mi * 16 + gg + 8] = s1;
            }
        }
    }
    __syncthreads();

    // --- softmax over 512 (scale 1/16) ---
    float e0 = se[tid], e1 = se[tid + 256];
    float m = fmaxf(e0, e1);
    #pragma unroll
    for (int off = 16; off; off >>= 1) m = fmaxf(m, __shfl_xor_sync(0xffffffffu, m, off));
    if (lane == 0) sred[warp] = m;
    __syncthreads();
    float M = fmaxf(fmaxf(fmaxf(sred[0], sred[1]), fmaxf(sred[2], sred[3])),
                    fmaxf(fmaxf(sred[4], sred[5]), fmaxf(sred[6], sred[7])));
    float v0 = __expf((e0 - M) * 0.0625f);
    float v1 = __expf((e1 - M) * 0.0625f);
    float s = v0 + v1;
    #pragma unroll
    for (int off = 16; off; off >>= 1) s += __shfl_xor_sync(0xffffffffu, s, off);
    if (lane == 0) sred[8 + warp] = s;
    se[tid] = v0; se[tid + 256] = v1;
    __syncthreads();
    float inv = 1.f / (sred[8] + sred[9] + sred[10] + sred[11] +
                       sred[12] + sred[13] + sred[14] + sred[15]);

    // --- ctx[d] = sum_l beta[l]*H[b,l,d] ---
    {
        int q = tid & 15, part = tid >> 4;
        float a[8] = {0.f, 0.f, 0.f, 0.f, 0.f, 0.f, 0.f, 0.f};
        #pragma unroll 4
        for (int l = part; l < SEQL; l += 16) {
            float bl = se[l];
            uint4 v = *(const uint4*)(sH + l * SH_STRIDE + q * 8);
            const __nv_bfloat162* h2 = (const __nv_bfloat162*)&v;
            #pragma unroll
            for (int i = 0; i < 4; i++) {
                float2 f = __bfloat1622float2(h2[i]);
                a[2 * i]     += bl * f.x;
                a[2 * i + 1] += bl * f.y;
            }
        }
        #pragma unroll
        for (int i = 0; i < 8; i++) sctxp[part * 128 + q * 8 + i] = a[i];
        __syncthreads();
        if (tid < 128) {
            float sum = 0.f;
            #pragma unroll
            for (int p = 0; p < 16; p++) sum += sctxp[p * 128 + tid];
            g_ctx[b * IND + tid] = sum * inv;
        }
    }
}

// ---------------- kernel 3: gates via tf32 mma, cp.async double-buffered ----------------
__global__ __launch_bounds__(256) void gates_kernel(
    const float* __restrict__ W, const float* __restrict__ U,
    const float* __restrict__ bias, const float* __restrict__ Wy, int t)
{
    __shared__ float As[2][64][36];
    __shared__ float Bs[2][32][72];
    int tid = threadIdx.x;
    int warp = tid >> 5, lane = tid & 31;
    int wm = warp & 3, wn = warp >> 2;
    int n0 = blockIdx.x * 64, b0 = blockIdx.y * 64;
    float acc[4][4] = {};

    // copy one 32-wide k-chunk into buffer buf
    auto copy_chunk = [&](int kc, int buf) {
        // A: 64 rows x 32 floats
        #pragma unroll
        for (int i = tid; i < 512; i += 256) {
            int row = i >> 3, seg = i & 7;
            const float* src = (kc < 4)
                ? (g_ctx + (size_t)(b0 + row) * IND + kc * 32 + seg * 4)
                : (g_h   + (size_t)(b0 + row) * HID + (kc * 32 - IND) + seg * 4);
            uint32_t dst = (uint32_t)__cvta_generic_to_shared(&As[buf][row][seg * 4]);
            cp_async16(dst, src);
        }
        // B: 32 k x 64 floats
        #pragma unroll
        for (int i = tid; i < 512; i += 256) {
            int k = i >> 4, seg = i & 15;
            int kg = kc * 32 + k;
            const float* src = (kg < IND)
                ? (W + (size_t)kg * (TT * 1024) + (size_t)t * 1024 + n0 + seg * 4)
                : (U + (size_t)(kg - IND) * (TT * 1024) + (size_t)t * 1024 + n0 + seg * 4);
            uint32_t dst = (uint32_t)__cvta_generic_to_shared(&Bs[buf][k][seg * 4]);
            cp_async16(dst, src);
        }
    };

    copy_chunk(0, 0); cp_commit();
    copy_chunk(1, 1); cp_commit();

    for (int kc = 0; kc < 12; kc++) {
        cp_wait<1>();
        __syncthreads();
        int buf = kc & 1;
        int ar = wm * 16 + (lane >> 2);
        int bk = lane & 3;
        int bn = wn * 32 + (lane >> 2);
        #pragma unroll
        for (int ks = 0; ks < 4; ks++) {
            uint32_t a[4];
            int ac = ks * 8 + (lane & 3);
            a[0] = __float_as_uint(As[buf][ar][ac]);
            a[1] = __float_as_uint(As[buf][ar + 8][ac]);
            a[2] = __float_as_uint(As[buf][ar][ac + 4]);
            a[3] = __float_as_uint(As[buf][ar + 8][ac + 4]);
            #pragma unroll
            for (int nt = 0; nt < 4; nt++) {
                uint32_t b0r = __float_as_uint(Bs[buf][ks * 8 + bk][bn + nt * 8]);
                uint32_t b1r = __float_as_uint(Bs[buf][ks * 8 + bk + 4][bn + nt * 8]);
                mma_tf32(acc[nt], a, b0r, b1r);
            }
        }
        __syncthreads();
        if (kc + 2 < 12) copy_chunk(kc + 2, buf);
        cp_commit();   // empty group when no copies — keeps wait<1> accounting simple
    }

    int r0 = b0 + wm * 16 + (lane >> 2);
    float y0v = g_y[r0], y1v = g_y[r0 + 8];
    #pragma unroll
    for (int nt = 0; nt < 4; nt++) {
        int n = n0 + wn * 32 + nt * 8 + (lane & 3) * 2;
        float bb0 = bias[t * 1024 + n],   bb1 = bias[t * 1024 + n + 1];
        float wy0 = Wy[t * 1024 + n],     wy1 = Wy[t * 1024 + n + 1];
        g_gates[(size_t)r0 * 1024 + n]           = acc[nt][0] + bb0 + y0v * wy0;
        g_gates[(size_t)r0 * 1024 + n + 1]       = acc[nt][1] + bb1 + y0v * wy1;
        g_gates[(size_t)(r0 + 8) * 1024 + n]     = acc[nt][2] + bb0 + y1v * wy0;
        g_gates[(size_t)(r0 + 8) * 1024 + n + 1] = acc[nt][3] + bb1 + y1v * wy1;
    }
}

// ---------------- kernel 4: cell update + y projection + outputs ----------------
__global__ void update_kernel(const float* __restrict__ fcw, const float* __restrict__ fcb,
                              int t, float* __restrict__ outy, float* __restrict__ outh)
{
    __shared__ float red[8];
    int b = blockIdx.x, j = threadIdx.x;
    size_t gi = (size_t)b * 1024;
    float i_ = 1.f / (1.f + __expf(-g_gates[gi + j]));
    float f_ = 1.f / (1.f + __expf(-g_gates[gi + 256 + j]));
    float gv = tanhf(g_gates[gi + 512 + j]);
    float o_ = 1.f / (1.f + __expf(-g_gates[gi + 768 + j]));
    float c = f_ * g_c[b * HID + j] + i_ * gv;
    float h = o_ * tanhf(c);
    g_c[b * HID + j] = c;
    g_h[b * HID + j] = h;
    outh[(size_t)b * TT * HID + (size_t)t * HID + j] = h;

    float p = h * fcw[t * HID + j];
    #pragma unroll
    for (int off = 16; off; off >>= 1) p += __shfl_xor_sync(0xffffffffu, p, off);
    int lane = j & 31, w = j >> 5;
    if (lane == 0) red[w] = p;
    __syncthreads();
    if (j == 0) {
        float ssum = red[0] + red[1] + red[2] + red[3] +
                     red[4] + red[5] + red[6] + red[7] + fcb[t];
        g_y[b] = ssum;
        outy[b * TT + t] = ssum;
    }
}

// ---------------- launch ----------------
extern "C" void kernel_launch(void* const* d_in, const int* in_sizes, int n_in,
                              void* d_out, int out_size)
{
    const float* H    = (const float*)d_in[0];
    const float* y0   = (const float*)d_in[1];
    const float* emb  = (const float*)d_in[2];
    const float* Wa   = (const float*)d_in[3];
    const float* Ua   = (const float*)d_in[4];
    const float* ba   = (const float*)d_in[5];
    const float* Va   = (const float*)d_in[6];
    const float* W    = (const float*)d_in[7];
    const float* U    = (const float*)d_in[8];
    const float* bias = (const float*)d_in[9];
    const float* Wy   = (const float*)d_in[10];
    const float* fcw  = (const float*)d_in[11];
    const float* fcb  = (const float*)d_in[12];

    float* outy = (float*)d_out;                 // (B, 24)
    float* outh = outy + (size_t)BB * TT;        // (B, 24, 256)

    cudaFuncSetAttribute(attn_kernel, cudaFuncAttributeMaxDynamicSharedMemorySize, ATTN_SMEM);

    convert_H<<<(BB * SEQL * IND / 4) / 256, 256>>>(H);
    init_state<<<BB, 256>>>(emb, y0);
    for (int t = 0; t < TT; t++) {
        attn_kernel<<<BB, 256, ATTN_SMEM>>>(Wa, Ua, ba, Va, t);
        gates_kernel<<<dim3(16, 8), 256>>>(W, U, bias, Wy, t);
        update_kernel<<<BB, 256>>>(fcw, fcb, t, outy, outh);
    }
}